// round 14
// baseline (speedup 1.0000x reference)
#include <cuda_runtime.h>
#include <cuda_bf16.h>
#include <cuda_fp16.h>
#include <cstdint>
#include <math.h>

#define T_TOK  4096
#define HID    4096
#define IMOE   1024
#define ISH    4096
#define NEXP   16
#define NPAIR  8192
#define MAX_MT 80
#define NSTG   4

// ---------------------------------------------------------------------------
// Static device scratch
// ---------------------------------------------------------------------------
static __device__ __half g_xs   [(size_t)T_TOK * HID];
static __device__ __half g_wsgu [(size_t)2*ISH * HID];
static __device__ __half g_wsd  [(size_t)HID * ISH];
static __device__ __half g_wgu  [(size_t)NEXP * 2*IMOE * HID];
static __device__ __half g_wd   [(size_t)NEXP * HID * IMOE];
static __device__ __half g_actsh[(size_t)T_TOK * ISH];
static __device__ __half g_actp [(size_t)NPAIR * IMOE];
static __device__ float  g_y    [(size_t)NPAIR * HID];

static __device__ int   g_counts[NEXP];
static __device__ int   g_offs[NEXP + 1];
static __device__ int   g_cursor[NEXP];
static __device__ int   g_eid[NPAIR];
static __device__ float g_wgt[NPAIR];
static __device__ int   g_perm[NPAIR];
static __device__ int   g_p2p[NPAIR];
static __device__ int   g_te[MAX_MT], g_tp0[MAX_MT], g_tcnt[MAX_MT];
static __device__ int   g_nmt[1];

// ---------------------------------------------------------------------------
// PTX helpers (Ampere-class only; proven on this harness)
// ---------------------------------------------------------------------------
__device__ __forceinline__ void cp16(uint32_t s, const void* g, int src_bytes) {
    asm volatile("cp.async.cg.shared.global [%0], [%1], 16, %2;\n"
                 :: "r"(s), "l"(g), "r"(src_bytes));
}
__device__ __forceinline__ void cp_commit() { asm volatile("cp.async.commit_group;\n"); }
__device__ __forceinline__ void cp_wait0()  { asm volatile("cp.async.wait_group 0;\n"); }
__device__ __forceinline__ void cp_wait1()  { asm volatile("cp.async.wait_group 1;\n"); }
__device__ __forceinline__ void cp_wait2()  { asm volatile("cp.async.wait_group 2;\n"); }

__device__ __forceinline__ void ldsm4(uint32_t* r, uint32_t a) {
    asm volatile("ldmatrix.sync.aligned.m8n8.x4.shared.b16 {%0,%1,%2,%3}, [%4];\n"
                 : "=r"(r[0]), "=r"(r[1]), "=r"(r[2]), "=r"(r[3]) : "r"(a));
}
__device__ __forceinline__ void ldsm2(uint32_t* r, uint32_t a) {
    asm volatile("ldmatrix.sync.aligned.m8n8.x2.shared.b16 {%0,%1}, [%2];\n"
                 : "=r"(r[0]), "=r"(r[1]) : "r"(a));
}
__device__ __forceinline__ void mma16816(float* c, const uint32_t* a, const uint32_t* b) {
    asm volatile("mma.sync.aligned.m16n8k16.row.col.f32.f16.f16.f32 "
                 "{%0,%1,%2,%3}, {%4,%5,%6,%7}, {%8,%9}, {%0,%1,%2,%3};\n"
                 : "+f"(c[0]), "+f"(c[1]), "+f"(c[2]), "+f"(c[3])
                 : "r"(a[0]), "r"(a[1]), "r"(a[2]), "r"(a[3]), "r"(b[0]), "r"(b[1]));
}

// XOR-swizzled smem offset: 128-byte rows (64 f16), 8x 16B chunks per row.
__device__ __forceinline__ uint32_t swz(uint32_t row, uint32_t chunk) {
    return (row << 7) + (((chunk ^ (row & 7u)) & 7u) << 4);
}

__device__ __forceinline__ float silu_mul(float g, float u) {
    return (g / (1.f + expf(-g))) * u;
}

// ---------------------------------------------------------------------------
// GEMM: CTA tile 128x256x64, warp tile 64x64, 256 threads, 4-stage cp.async
// (192KB smem, 1 CTA/SM), fp16 in / fp32 accum.
// MODE 0 dense; MODE 1 grouped, A rows via g_perm; MODE 2 grouped identity.
// SWIGLU 0: fp32 C, 256 cols per tile (B has Nact rows).
// SWIGLU 1: B has 2*Nact rows (gu). B-tile 256 rows = 8 slabs of 32 rows
//           [16 g | 16 u] covering act cols nt*128..+127; epilogue applies
//           silu(g)*u and writes fp16 act [*, Nact].
// ---------------------------------------------------------------------------
template <int MODE, int SWIGLU>
__global__ void __launch_bounds__(256, 1)
gemm_k(const __half* __restrict__ A, const __half* __restrict__ B,
       void* __restrict__ Cout, int Nact, int K, size_t Bstride, int ntiles)
{
    const int tid  = threadIdx.x;
    const int warp = tid >> 5;
    const int lane = tid & 31;

    int mt_row0, cnt, nt, e = 0;
    if (MODE == 0) {
        int per = 8 * ntiles;                 // m-tile count must be mult of 8
        int chunk = blockIdx.x / per, rem = blockIdx.x - chunk * per;
        mt_row0 = (chunk * 8 + (rem & 7)) << 7;
        nt = rem >> 3;
        cnt = 128;
    } else {
        if ((int)blockIdx.y >= g_nmt[0]) return;
        nt      = blockIdx.x;
        e       = g_te[blockIdx.y];
        mt_row0 = g_tp0[blockIdx.y];
        cnt     = g_tcnt[blockIdx.y];
    }
    const __half* Bp = B + (size_t)e * Bstride;

    extern __shared__ char smem[];   // 4 stages x (A 16KB + B 32KB)
    const uint32_t smB = (uint32_t)__cvta_generic_to_shared(smem);

    const int NIT = K >> 6;

    auto load_tiles = [&](int stage, int it) {
        int kk = it << 6;
        uint32_t aB = smB + stage * 49152;
        uint32_t bB = aB + 16384;
#pragma unroll
        for (int i = 0; i < 12; i++) {
            int lin = i * 256 + tid;
            if (i < 4) {                       // A: 128 rows x 128B
                int row = lin >> 3, ch = lin & 7;
                size_t ga; int vb = 16;
                if (MODE == 0) {
                    ga = (size_t)(mt_row0 + row) * K + kk + ch * 8;
                } else if (MODE == 1) {
                    int ok = (row < cnt);
                    int rg = ok ? g_perm[mt_row0 + row] : 0;
                    vb = ok ? 16 : 0;
                    ga = (size_t)rg * K + kk + ch * 8;
                } else {
                    int ok = (row < cnt);
                    int rg = ok ? (mt_row0 + row) : 0;
                    vb = ok ? 16 : 0;
                    ga = (size_t)rg * K + kk + ch * 8;
                }
                cp16(aB + swz(row, ch), A + ga, vb);
            } else {                           // B: 256 rows x 128B
                int l2 = lin - 1024;
                int row = l2 >> 3, ch = l2 & 7;
                int brow;
                if (SWIGLU) {
                    int s = row >> 5, w = row & 31;       // slab s: [16 g | 16 u]
                    brow = (w < 16) ? (nt * 128 + s * 16 + w)
                                    : (Nact + nt * 128 + s * 16 + (w - 16));
                } else {
                    brow = nt * 256 + row;
                }
                cp16(bB + swz(row, ch), Bp + (size_t)brow * K + kk + ch * 8, 16);
            }
        }
        cp_commit();
    };

    float acc[4][8][4];
#pragma unroll
    for (int a = 0; a < 4; a++)
#pragma unroll
        for (int b = 0; b < 8; b++)
#pragma unroll
            for (int c = 0; c < 4; c++) acc[a][b][c] = 0.f;

    const int wm = warp & 1;      // 0..1  (64-row slabs)
    const int wn = warp >> 1;     // 0..3  (64-B-row slabs)

    load_tiles(0, 0);
    load_tiles(1, 1);
    load_tiles(2, 2);

    for (int it = 0; it < NIT; ++it) {
        if (it + 2 < NIT) cp_wait2();
        else if (it + 1 < NIT) cp_wait1();
        else cp_wait0();
        __syncthreads();
        int cur = it & 3;
        if (it + 3 < NIT) load_tiles((it + 3) & 3, it + 3);

        uint32_t aB = smB + cur * 49152;
        uint32_t bB = aB + 16384;
#pragma unroll
        for (int kk = 0; kk < 4; kk++) {
            uint32_t afr[4][4], bfr[8][2];
#pragma unroll
            for (int mi = 0; mi < 4; mi++) {
                int row = wm * 64 + mi * 16 + (lane & 15);
                int ch  = kk * 2 + ((lane >> 4) & 1);
                ldsm4(afr[mi], aB + swz(row, ch));
            }
#pragma unroll
            for (int ni = 0; ni < 8; ni++) {
                int row = wn * 64 + ni * 8 + (lane & 7);
                int ch  = kk * 2 + ((lane >> 3) & 1);
                ldsm2(bfr[ni], bB + swz(row, ch));
            }
#pragma unroll
            for (int mi = 0; mi < 4; mi++)
#pragma unroll
                for (int ni = 0; ni < 8; ni++)
                    mma16816(acc[mi][ni], afr[mi], bfr[ni]);
        }
        __syncthreads();
    }

    // ---------------- epilogue ----------------
#pragma unroll
    for (int mi = 0; mi < 4; mi++) {
        int lr0 = wm * 64 + mi * 16 + (lane >> 2);
        int lr1 = lr0 + 8;
        int v0 = (MODE == 0) || (lr0 < cnt);
        int v1 = (MODE == 0) || (lr1 < cnt);
        if (SWIGLU) {
            __half* act = (__half*)Cout;
            // warp covers slabs 2*wn and 2*wn+1; pairs (p, p+2) for p in {0,1,4,5}
#pragma unroll
            for (int pi = 0; pi < 4; pi++) {
                const int p = (pi & 1) | ((pi & 2) << 1);   // 0,1,4,5
                size_t col = nt * 128 + (2 * wn + (p >> 2)) * 16
                           + (p & 1) * 8 + 2 * (lane & 3);
                if (v0) {
                    __half2 h = __floats2half2_rn(
                        silu_mul(acc[mi][p][0], acc[mi][p + 2][0]),
                        silu_mul(acc[mi][p][1], acc[mi][p + 2][1]));
                    *(__half2*)&act[(size_t)(mt_row0 + lr0) * Nact + col] = h;
                }
                if (v1) {
                    __half2 h = __floats2half2_rn(
                        silu_mul(acc[mi][p][2], acc[mi][p + 2][2]),
                        silu_mul(acc[mi][p][3], acc[mi][p + 2][3]));
                    *(__half2*)&act[(size_t)(mt_row0 + lr1) * Nact + col] = h;
                }
            }
        } else {
            float* C = (float*)Cout;
#pragma unroll
            for (int ni = 0; ni < 8; ni++) {
                size_t col = nt * 256 + wn * 64 + ni * 8 + 2 * (lane & 3);
                if (v0) {
                    float2 v = make_float2(acc[mi][ni][0], acc[mi][ni][1]);
                    *(float2*)&C[(size_t)(mt_row0 + lr0) * Nact + col] = v;
                }
                if (v1) {
                    float2 v = make_float2(acc[mi][ni][2], acc[mi][ni][3]);
                    *(float2*)&C[(size_t)(mt_row0 + lr1) * Nact + col] = v;
                }
            }
        }
    }
}

// ---------------------------------------------------------------------------
// Elementwise / router kernels (unchanged from R11)
// ---------------------------------------------------------------------------
__global__ void cvt_kernel(const float4* __restrict__ src,
                           uint2* __restrict__ dst, size_t n4)
{
    size_t i = (size_t)blockIdx.x * 256 + threadIdx.x;
    if (i >= n4) return;
    float4 v = src[i];
    __half2 lo = __floats2half2_rn(v.x, v.y);
    __half2 hi = __floats2half2_rn(v.z, v.w);
    uint2 o;
    o.x = *(uint32_t*)&lo;
    o.y = *(uint32_t*)&hi;
    dst[i] = o;
}

__global__ void init_kernel() {
    if (threadIdx.x < NEXP) g_counts[threadIdx.x] = 0;
}

__global__ void router_kernel(const float* __restrict__ x, const float* __restrict__ gw)
{
    __shared__ float slog[NEXP];
    int t = blockIdx.x;
    const float* xr = x + (size_t)t * HID;
    int tid = threadIdx.x;
    int e = tid >> 3, g = tid & 7;
    float s = 0.f;
    const float* w = gw + (size_t)e * HID;
    for (int k = g; k < HID; k += 8) s += xr[k] * w[k];
#pragma unroll
    for (int o = 4; o > 0; o >>= 1) s += __shfl_down_sync(0xffffffffu, s, o, 8);
    if (g == 0) slog[e] = s;
    __syncthreads();
    if (tid == 0) {
        int i0 = 0;
        float b0 = slog[0];
        for (int k = 1; k < NEXP; k++) if (slog[k] > b0) { b0 = slog[k]; i0 = k; }
        int i1 = -1;
        float b1 = -3.4e38f;
        for (int k = 0; k < NEXP; k++) {
            if (k == i0) continue;
            if (slog[k] > b1) { b1 = slog[k]; i1 = k; }
        }
        float m  = fmaxf(b0, b1);
        float e0 = expf(b0 - m), e1 = expf(b1 - m);
        float inv = 1.f / (e0 + e1);
        g_eid[2 * t] = i0;       g_eid[2 * t + 1] = i1;
        g_wgt[2 * t] = e0 * inv; g_wgt[2 * t + 1] = e1 * inv;
        atomicAdd(&g_counts[i0], 1);
        atomicAdd(&g_counts[i1], 1);
    }
}

__global__ void scan_kernel()
{
    if (threadIdx.x != 0 || blockIdx.x != 0) return;
    int off = 0;
    for (int e = 0; e < NEXP; e++) {
        g_offs[e] = off; g_cursor[e] = off; off += g_counts[e];
    }
    g_offs[NEXP] = off;
    int t = 0;
    for (int e = 0; e < NEXP; e++) {
        int c = g_counts[e];
        for (int j = 0; j * 128 < c; j++) {
            g_te[t]  = e;
            g_tp0[t] = g_offs[e] + j * 128;
            int rem  = c - j * 128;
            g_tcnt[t] = rem < 128 ? rem : 128;
            t++;
        }
    }
    g_nmt[0] = t;
}

__global__ void scatter_kernel()
{
    int p = blockIdx.x * 256 + threadIdx.x;
    if (p >= NPAIR) return;
    int e = g_eid[p];
    int pos = atomicAdd(&g_cursor[e], 1);
    g_perm[pos] = p >> 1;
    g_p2p[p] = pos;
}

__global__ void combine_kernel(float* __restrict__ out)
{
    size_t i4 = (size_t)blockIdx.x * 256 + threadIdx.x;
    if (i4 >= (size_t)T_TOK * HID / 4) return;
    size_t i = i4 << 2;
    int t = (int)(i >> 12);
    int h = (int)(i & 4095);
    int p0 = g_p2p[2 * t], p1 = g_p2p[2 * t + 1];
    float w0 = g_wgt[2 * t], w1 = g_wgt[2 * t + 1];
    float4 y0 = *(const float4*)&g_y[(size_t)p0 * HID + h];
    float4 y1 = *(const float4*)&g_y[(size_t)p1 * HID + h];
    float4 o  = *(float4*)&out[i];
    o.x += w0 * y0.x + w1 * y1.x;
    o.y += w0 * y0.y + w1 * y1.y;
    o.z += w0 * y0.z + w1 * y1.z;
    o.w += w0 * y0.w + w1 * y1.w;
    *(float4*)&out[i] = o;
}

// ---------------------------------------------------------------------------
// Launch
// ---------------------------------------------------------------------------
extern "C" void kernel_launch(void* const* d_in, const int* in_sizes, int n_in,
                              void* d_out, int out_size)
{
    const float* x    = (const float*)d_in[0];
    const float* gw   = (const float*)d_in[1];
    const float* wgu  = (const float*)d_in[2];
    const float* wd   = (const float*)d_in[3];
    const float* swgu = (const float*)d_in[4];
    const float* swd  = (const float*)d_in[5];
    float* out = (float*)d_out;

    void *p_xs, *p_wsgu, *p_wsd, *p_wgu, *p_wd, *p_actsh, *p_actp, *p_y;
    cudaGetSymbolAddress(&p_xs,    g_xs);
    cudaGetSymbolAddress(&p_wsgu,  g_wsgu);
    cudaGetSymbolAddress(&p_wsd,   g_wsd);
    cudaGetSymbolAddress(&p_wgu,   g_wgu);
    cudaGetSymbolAddress(&p_wd,    g_wd);
    cudaGetSymbolAddress(&p_actsh, g_actsh);
    cudaGetSymbolAddress(&p_actp,  g_actp);
    cudaGetSymbolAddress(&p_y,     g_y);

    const int SMEM = NSTG * 49152;   // 196608, 1 CTA/SM
    cudaFuncSetAttribute(gemm_k<0,1>, cudaFuncAttributeMaxDynamicSharedMemorySize, SMEM);
    cudaFuncSetAttribute(gemm_k<0,0>, cudaFuncAttributeMaxDynamicSharedMemorySize, SMEM);
    cudaFuncSetAttribute(gemm_k<1,1>, cudaFuncAttributeMaxDynamicSharedMemorySize, SMEM);
    cudaFuncSetAttribute(gemm_k<2,0>, cudaFuncAttributeMaxDynamicSharedMemorySize, SMEM);

    auto blk4 = [](size_t n) { return (unsigned)((n / 4 + 255) / 256); };

    // fp32 -> fp16 converts
    cvt_kernel<<<blk4((size_t)T_TOK * HID),           256>>>((const float4*)x,    (uint2*)p_xs,   (size_t)T_TOK * HID / 4);
    cvt_kernel<<<blk4((size_t)2 * ISH * HID),         256>>>((const float4*)swgu, (uint2*)p_wsgu, (size_t)2 * ISH * HID / 4);
    cvt_kernel<<<blk4((size_t)HID * ISH),             256>>>((const float4*)swd,  (uint2*)p_wsd,  (size_t)HID * ISH / 4);
    cvt_kernel<<<blk4((size_t)NEXP * 2 * IMOE * HID), 256>>>((const float4*)wgu,  (uint2*)p_wgu,  (size_t)NEXP * 2 * IMOE * HID / 4);
    cvt_kernel<<<blk4((size_t)NEXP * HID * IMOE),     256>>>((const float4*)wd,   (uint2*)p_wd,   (size_t)NEXP * HID * IMOE / 4);

    // router + grouping metadata
    init_kernel<<<1, 32>>>();
    router_kernel<<<T_TOK, 128>>>(x, gw);
    scan_kernel<<<1, 32>>>();
    scatter_kernel<<<(NPAIR + 255) / 256, 256>>>();

    // shared MLP: gate_up (fused swiglu, 128 act cols/tile) then down -> out
    gemm_k<0,1><<<(T_TOK / 128) * (ISH / 128), 256, SMEM>>>(
        (const __half*)p_xs, (const __half*)p_wsgu, p_actsh,
        ISH, HID, 0, ISH / 128);
    gemm_k<0,0><<<(T_TOK / 128) * (HID / 256), 256, SMEM>>>(
        (const __half*)p_actsh, (const __half*)p_wsd, (void*)out,
        HID, ISH, 0, HID / 256);

    // grouped MoE: gate_up (gather + fused swiglu) then down -> g_y
    gemm_k<1,1><<<dim3(IMOE / 128, MAX_MT), 256, SMEM>>>(
        (const __half*)p_xs, (const __half*)p_wgu, p_actp,
        IMOE, HID, (size_t)(2 * IMOE) * HID, 0);
    gemm_k<2,0><<<dim3(HID / 256, MAX_MT), 256, SMEM>>>(
        (const __half*)p_actp, (const __half*)p_wd, p_y,
        HID, IMOE, (size_t)HID * IMOE, 0);

    // combine: out += w0*y[p0] + w1*y[p1]
    combine_kernel<<<blk4((size_t)T_TOK * HID), 256>>>(out);
}

// round 15
// speedup vs baseline: 1.0914x; 1.0914x over previous
#include <cuda_runtime.h>
#include <cuda_bf16.h>
#include <cuda_fp16.h>
#include <cstdint>
#include <math.h>

#define T_TOK  4096
#define HID    4096
#define IMOE   1024
#define ISH    4096
#define NEXP   16
#define NPAIR  8192
#define MAX_MT 80
#define NSTG   3

// ---------------------------------------------------------------------------
// Static device scratch
// ---------------------------------------------------------------------------
static __device__ __half g_xs   [(size_t)T_TOK * HID];
static __device__ __half g_wsgu [(size_t)2*ISH * HID];
static __device__ __half g_wsd  [(size_t)HID * ISH];
static __device__ __half g_wgu  [(size_t)NEXP * 2*IMOE * HID];
static __device__ __half g_wd   [(size_t)NEXP * HID * IMOE];
static __device__ __half g_actsh[(size_t)T_TOK * ISH];
static __device__ __half g_actp [(size_t)NPAIR * IMOE];
static __device__ float  g_y    [(size_t)NPAIR * HID];

static __device__ int   g_counts[NEXP];
static __device__ int   g_offs[NEXP + 1];
static __device__ int   g_cursor[NEXP];
static __device__ int   g_eid[NPAIR];
static __device__ float g_wgt[NPAIR];
static __device__ int   g_perm[NPAIR];
static __device__ int   g_p2p[NPAIR];
static __device__ int   g_te[MAX_MT], g_tp0[MAX_MT], g_tcnt[MAX_MT];
static __device__ int   g_nmt[1];

// ---------------------------------------------------------------------------
// PTX helpers (proven on this harness)
// ---------------------------------------------------------------------------
__device__ __forceinline__ void cp16(uint32_t s, const void* g, int src_bytes) {
    asm volatile("cp.async.cg.shared.global [%0], [%1], 16, %2;\n"
                 :: "r"(s), "l"(g), "r"(src_bytes));
}
__device__ __forceinline__ void cp_commit() { asm volatile("cp.async.commit_group;\n"); }
__device__ __forceinline__ void cp_wait0()  { asm volatile("cp.async.wait_group 0;\n"); }
__device__ __forceinline__ void cp_wait1()  { asm volatile("cp.async.wait_group 1;\n"); }

__device__ __forceinline__ void ldsm4(uint32_t* r, uint32_t a) {
    asm volatile("ldmatrix.sync.aligned.m8n8.x4.shared.b16 {%0,%1,%2,%3}, [%4];\n"
                 : "=r"(r[0]), "=r"(r[1]), "=r"(r[2]), "=r"(r[3]) : "r"(a));
}
__device__ __forceinline__ void ldsm2(uint32_t* r, uint32_t a) {
    asm volatile("ldmatrix.sync.aligned.m8n8.x2.shared.b16 {%0,%1}, [%2];\n"
                 : "=r"(r[0]), "=r"(r[1]) : "r"(a));
}
__device__ __forceinline__ void mma16816(float* c, const uint32_t* a, const uint32_t* b) {
    asm volatile("mma.sync.aligned.m16n8k16.row.col.f32.f16.f16.f32 "
                 "{%0,%1,%2,%3}, {%4,%5,%6,%7}, {%8,%9}, {%0,%1,%2,%3};\n"
                 : "+f"(c[0]), "+f"(c[1]), "+f"(c[2]), "+f"(c[3])
                 : "r"(a[0]), "r"(a[1]), "r"(a[2]), "r"(a[3]), "r"(b[0]), "r"(b[1]));
}

// XOR-swizzled smem offset: 128-byte rows (64 f16), 8x 16B chunks per row.
__device__ __forceinline__ uint32_t swz(uint32_t row, uint32_t chunk) {
    return (row << 7) + (((chunk ^ (row & 7u)) & 7u) << 4);
}

__device__ __forceinline__ float silu_mul(float g, float u) {
    return (g / (1.f + expf(-g))) * u;
}

// ---------------------------------------------------------------------------
// GEMM: CTA tile 128x128x64, 128 threads (2x2 warps, warp tile 64x64),
// 3-stage cp.async (96KB smem, 2 CTAs/SM), fp16 in / fp32 accum.
// MODE 0 dense; MODE 1 grouped, A rows via g_perm; MODE 2 grouped identity.
// SWIGLU 0: fp32 C, 128 cols per tile (B has Nact rows).
// SWIGLU 1: B has 2*Nact rows (gu). B-tile 128 rows = 4 slabs of 32 rows
//           [16 g | 16 u] covering act cols nt*64..+63; epilogue applies
//           silu(g)*u and writes fp16 act [*, Nact].
// ---------------------------------------------------------------------------
template <int MODE, int SWIGLU>
__global__ void __launch_bounds__(128, 2)
gemm_k(const __half* __restrict__ A, const __half* __restrict__ B,
       void* __restrict__ Cout, int Nact, int K, size_t Bstride, int ntiles)
{
    const int tid  = threadIdx.x;
    const int warp = tid >> 5;
    const int lane = tid & 31;

    int mt_row0, cnt, nt, e = 0;
    if (MODE == 0) {
        int per = 8 * ntiles;                 // m-tile count must be mult of 8
        int chunk = blockIdx.x / per, rem = blockIdx.x - chunk * per;
        mt_row0 = (chunk * 8 + (rem & 7)) << 7;
        nt = rem >> 3;
        cnt = 128;
    } else {
        if ((int)blockIdx.y >= g_nmt[0]) return;
        nt      = blockIdx.x;
        e       = g_te[blockIdx.y];
        mt_row0 = g_tp0[blockIdx.y];
        cnt     = g_tcnt[blockIdx.y];
    }
    const __half* Bp = B + (size_t)e * Bstride;

    extern __shared__ char smem[];   // 3 stages x (A 16KB + B 16KB)
    const uint32_t smB = (uint32_t)__cvta_generic_to_shared(smem);

    const int NIT = K >> 6;

    auto load_tiles = [&](int stage, int it) {
        int kk = it << 6;
        uint32_t aB = smB + stage * 32768;
        uint32_t bB = aB + 16384;
#pragma unroll
        for (int i = 0; i < 8; i++) {
            int lin = i * 128 + tid;
            int row = lin >> 3, ch = lin & 7;
            // A tile row
            size_t ga; int vb = 16;
            if (MODE == 0) {
                ga = (size_t)(mt_row0 + row) * K + kk + ch * 8;
            } else if (MODE == 1) {
                int ok = (row < cnt);
                int rg = ok ? g_perm[mt_row0 + row] : 0;
                vb = ok ? 16 : 0;
                ga = (size_t)rg * K + kk + ch * 8;
            } else {
                int ok = (row < cnt);
                int rg = ok ? (mt_row0 + row) : 0;
                vb = ok ? 16 : 0;
                ga = (size_t)rg * K + kk + ch * 8;
            }
            cp16(aB + swz(row, ch), A + ga, vb);
            // B tile row
            int brow;
            if (SWIGLU) {
                int s = row >> 5, w = row & 31;       // slab s: [16 g | 16 u]
                brow = (w < 16) ? (nt * 64 + s * 16 + w)
                                : (Nact + nt * 64 + s * 16 + (w - 16));
            } else {
                brow = nt * 128 + row;
            }
            cp16(bB + swz(row, ch), Bp + (size_t)brow * K + kk + ch * 8, 16);
        }
        cp_commit();
    };

    float acc[4][8][4];
#pragma unroll
    for (int a = 0; a < 4; a++)
#pragma unroll
        for (int b = 0; b < 8; b++)
#pragma unroll
            for (int c = 0; c < 4; c++) acc[a][b][c] = 0.f;

    const int wm = warp & 1;      // 0..1  (64-row slabs of A)
    const int wn = warp >> 1;     // 0..1  (64-row slabs of B)

    load_tiles(0, 0);
    load_tiles(1, 1);

    for (int it = 0; it < NIT; ++it) {
        if (it == NIT - 1) cp_wait0(); else cp_wait1();
        __syncthreads();
        int cur = it % NSTG;
        if (it + 2 < NIT) load_tiles((it + 2) % NSTG, it + 2);

        uint32_t aB = smB + cur * 32768;
        uint32_t bB = aB + 16384;
#pragma unroll
        for (int kk = 0; kk < 4; kk++) {
            uint32_t afr[4][4], bfr[8][2];
#pragma unroll
            for (int mi = 0; mi < 4; mi++) {
                int row = wm * 64 + mi * 16 + (lane & 15);
                int ch  = kk * 2 + ((lane >> 4) & 1);
                ldsm4(afr[mi], aB + swz(row, ch));
            }
#pragma unroll
            for (int ni = 0; ni < 8; ni++) {
                int row = wn * 64 + ni * 8 + (lane & 7);
                int ch  = kk * 2 + ((lane >> 3) & 1);
                ldsm2(bfr[ni], bB + swz(row, ch));
            }
#pragma unroll
            for (int mi = 0; mi < 4; mi++)
#pragma unroll
                for (int ni = 0; ni < 8; ni++)
                    mma16816(acc[mi][ni], afr[mi], bfr[ni]);
        }
        __syncthreads();
    }

    // ---------------- epilogue ----------------
#pragma unroll
    for (int mi = 0; mi < 4; mi++) {
        int lr0 = wm * 64 + mi * 16 + (lane >> 2);
        int lr1 = lr0 + 8;
        int v0 = (MODE == 0) || (lr0 < cnt);
        int v1 = (MODE == 0) || (lr1 < cnt);
        if (SWIGLU) {
            __half* act = (__half*)Cout;
            // warp covers slabs 2*wn, 2*wn+1: ni pairs (p, p+2), p in {0,1,4,5}
#pragma unroll
            for (int pi = 0; pi < 4; pi++) {
                const int p = (pi & 1) | ((pi & 2) << 1);   // 0,1,4,5
                size_t col = nt * 64 + (2 * wn + (p >> 2)) * 16
                           + (p & 1) * 8 + 2 * (lane & 3);
                if (v0) {
                    __half2 h = __floats2half2_rn(
                        silu_mul(acc[mi][p][0], acc[mi][p + 2][0]),
                        silu_mul(acc[mi][p][1], acc[mi][p + 2][1]));
                    *(__half2*)&act[(size_t)(mt_row0 + lr0) * Nact + col] = h;
                }
                if (v1) {
                    __half2 h = __floats2half2_rn(
                        silu_mul(acc[mi][p][2], acc[mi][p + 2][2]),
                        silu_mul(acc[mi][p][3], acc[mi][p + 2][3]));
                    *(__half2*)&act[(size_t)(mt_row0 + lr1) * Nact + col] = h;
                }
            }
        } else {
            float* C = (float*)Cout;
#pragma unroll
            for (int ni = 0; ni < 8; ni++) {
                size_t col = nt * 128 + wn * 64 + ni * 8 + 2 * (lane & 3);
                if (v0) {
                    float2 v = make_float2(acc[mi][ni][0], acc[mi][ni][1]);
                    *(float2*)&C[(size_t)(mt_row0 + lr0) * Nact + col] = v;
                }
                if (v1) {
                    float2 v = make_float2(acc[mi][ni][2], acc[mi][ni][3]);
                    *(float2*)&C[(size_t)(mt_row0 + lr1) * Nact + col] = v;
                }
            }
        }
    }
}

// ---------------------------------------------------------------------------
// Elementwise / router kernels (unchanged from R11)
// ---------------------------------------------------------------------------
__global__ void cvt_kernel(const float4* __restrict__ src,
                           uint2* __restrict__ dst, size_t n4)
{
    size_t i = (size_t)blockIdx.x * 256 + threadIdx.x;
    if (i >= n4) return;
    float4 v = src[i];
    __half2 lo = __floats2half2_rn(v.x, v.y);
    __half2 hi = __floats2half2_rn(v.z, v.w);
    uint2 o;
    o.x = *(uint32_t*)&lo;
    o.y = *(uint32_t*)&hi;
    dst[i] = o;
}

__global__ void init_kernel() {
    if (threadIdx.x < NEXP) g_counts[threadIdx.x] = 0;
}

__global__ void router_kernel(const float* __restrict__ x, const float* __restrict__ gw)
{
    __shared__ float slog[NEXP];
    int t = blockIdx.x;
    const float* xr = x + (size_t)t * HID;
    int tid = threadIdx.x;
    int e = tid >> 3, g = tid & 7;
    float s = 0.f;
    const float* w = gw + (size_t)e * HID;
    for (int k = g; k < HID; k += 8) s += xr[k] * w[k];
#pragma unroll
    for (int o = 4; o > 0; o >>= 1) s += __shfl_down_sync(0xffffffffu, s, o, 8);
    if (g == 0) slog[e] = s;
    __syncthreads();
    if (tid == 0) {
        int i0 = 0;
        float b0 = slog[0];
        for (int k = 1; k < NEXP; k++) if (slog[k] > b0) { b0 = slog[k]; i0 = k; }
        int i1 = -1;
        float b1 = -3.4e38f;
        for (int k = 0; k < NEXP; k++) {
            if (k == i0) continue;
            if (slog[k] > b1) { b1 = slog[k]; i1 = k; }
        }
        float m  = fmaxf(b0, b1);
        float e0 = expf(b0 - m), e1 = expf(b1 - m);
        float inv = 1.f / (e0 + e1);
        g_eid[2 * t] = i0;       g_eid[2 * t + 1] = i1;
        g_wgt[2 * t] = e0 * inv; g_wgt[2 * t + 1] = e1 * inv;
        atomicAdd(&g_counts[i0], 1);
        atomicAdd(&g_counts[i1], 1);
    }
}

__global__ void scan_kernel()
{
    if (threadIdx.x != 0 || blockIdx.x != 0) return;
    int off = 0;
    for (int e = 0; e < NEXP; e++) {
        g_offs[e] = off; g_cursor[e] = off; off += g_counts[e];
    }
    g_offs[NEXP] = off;
    int t = 0;
    for (int e = 0; e < NEXP; e++) {
        int c = g_counts[e];
        for (int j = 0; j * 128 < c; j++) {
            g_te[t]  = e;
            g_tp0[t] = g_offs[e] + j * 128;
            int rem  = c - j * 128;
            g_tcnt[t] = rem < 128 ? rem : 128;
            t++;
        }
    }
    g_nmt[0] = t;
}

__global__ void scatter_kernel()
{
    int p = blockIdx.x * 256 + threadIdx.x;
    if (p >= NPAIR) return;
    int e = g_eid[p];
    int pos = atomicAdd(&g_cursor[e], 1);
    g_perm[pos] = p >> 1;
    g_p2p[p] = pos;
}

__global__ void combine_kernel(float* __restrict__ out)
{
    size_t i4 = (size_t)blockIdx.x * 256 + threadIdx.x;
    if (i4 >= (size_t)T_TOK * HID / 4) return;
    size_t i = i4 << 2;
    int t = (int)(i >> 12);
    int h = (int)(i & 4095);
    int p0 = g_p2p[2 * t], p1 = g_p2p[2 * t + 1];
    float w0 = g_wgt[2 * t], w1 = g_wgt[2 * t + 1];
    float4 y0 = *(const float4*)&g_y[(size_t)p0 * HID + h];
    float4 y1 = *(const float4*)&g_y[(size_t)p1 * HID + h];
    float4 o  = *(float4*)&out[i];
    o.x += w0 * y0.x + w1 * y1.x;
    o.y += w0 * y0.y + w1 * y1.y;
    o.z += w0 * y0.z + w1 * y1.z;
    o.w += w0 * y0.w + w1 * y1.w;
    *(float4*)&out[i] = o;
}

// ---------------------------------------------------------------------------
// Launch
// ---------------------------------------------------------------------------
extern "C" void kernel_launch(void* const* d_in, const int* in_sizes, int n_in,
                              void* d_out, int out_size)
{
    const float* x    = (const float*)d_in[0];
    const float* gw   = (const float*)d_in[1];
    const float* wgu  = (const float*)d_in[2];
    const float* wd   = (const float*)d_in[3];
    const float* swgu = (const float*)d_in[4];
    const float* swd  = (const float*)d_in[5];
    float* out = (float*)d_out;

    void *p_xs, *p_wsgu, *p_wsd, *p_wgu, *p_wd, *p_actsh, *p_actp, *p_y;
    cudaGetSymbolAddress(&p_xs,    g_xs);
    cudaGetSymbolAddress(&p_wsgu,  g_wsgu);
    cudaGetSymbolAddress(&p_wsd,   g_wsd);
    cudaGetSymbolAddress(&p_wgu,   g_wgu);
    cudaGetSymbolAddress(&p_wd,    g_wd);
    cudaGetSymbolAddress(&p_actsh, g_actsh);
    cudaGetSymbolAddress(&p_actp,  g_actp);
    cudaGetSymbolAddress(&p_y,     g_y);

    const int SMEM = NSTG * 32768;   // 98304, 2 CTAs/SM
    cudaFuncSetAttribute(gemm_k<0,1>, cudaFuncAttributeMaxDynamicSharedMemorySize, SMEM);
    cudaFuncSetAttribute(gemm_k<0,0>, cudaFuncAttributeMaxDynamicSharedMemorySize, SMEM);
    cudaFuncSetAttribute(gemm_k<1,1>, cudaFuncAttributeMaxDynamicSharedMemorySize, SMEM);
    cudaFuncSetAttribute(gemm_k<2,0>, cudaFuncAttributeMaxDynamicSharedMemorySize, SMEM);

    auto blk4 = [](size_t n) { return (unsigned)((n / 4 + 255) / 256); };

    // fp32 -> fp16 converts
    cvt_kernel<<<blk4((size_t)T_TOK * HID),           256>>>((const float4*)x,    (uint2*)p_xs,   (size_t)T_TOK * HID / 4);
    cvt_kernel<<<blk4((size_t)2 * ISH * HID),         256>>>((const float4*)swgu, (uint2*)p_wsgu, (size_t)2 * ISH * HID / 4);
    cvt_kernel<<<blk4((size_t)HID * ISH),             256>>>((const float4*)swd,  (uint2*)p_wsd,  (size_t)HID * ISH / 4);
    cvt_kernel<<<blk4((size_t)NEXP * 2 * IMOE * HID), 256>>>((const float4*)wgu,  (uint2*)p_wgu,  (size_t)NEXP * 2 * IMOE * HID / 4);
    cvt_kernel<<<blk4((size_t)NEXP * HID * IMOE),     256>>>((const float4*)wd,   (uint2*)p_wd,   (size_t)NEXP * HID * IMOE / 4);

    // router + grouping metadata
    init_kernel<<<1, 32>>>();
    router_kernel<<<T_TOK, 128>>>(x, gw);
    scan_kernel<<<1, 32>>>();
    scatter_kernel<<<(NPAIR + 255) / 256, 256>>>();

    // shared MLP: gate_up (fused swiglu, 64 act cols/tile) then down -> out
    gemm_k<0,1><<<(T_TOK / 128) * (ISH / 64), 128, SMEM>>>(
        (const __half*)p_xs, (const __half*)p_wsgu, p_actsh,
        ISH, HID, 0, ISH / 64);
    gemm_k<0,0><<<(T_TOK / 128) * (HID / 128), 128, SMEM>>>(
        (const __half*)p_actsh, (const __half*)p_wsd, (void*)out,
        HID, ISH, 0, HID / 128);

    // grouped MoE: gate_up (gather + fused swiglu) then down -> g_y
    gemm_k<1,1><<<dim3(IMOE / 64, MAX_MT), 128, SMEM>>>(
        (const __half*)p_xs, (const __half*)p_wgu, p_actp,
        IMOE, HID, (size_t)(2 * IMOE) * HID, 0);
    gemm_k<2,0><<<dim3(HID / 128, MAX_MT), 128, SMEM>>>(
        (const __half*)p_actp, (const __half*)p_wd, p_y,
        HID, IMOE, (size_t)HID * IMOE, 0);

    // combine: out += w0*y[p0] + w1*y[p1]
    combine_kernel<<<blk4((size_t)T_TOK * HID), 256>>>(out);
}

// round 16
// speedup vs baseline: 1.1009x; 1.0087x over previous
#include <cuda_runtime.h>
#include <cuda_bf16.h>
#include <cuda_fp16.h>
#include <cstdint>
#include <math.h>

#define T_TOK  4096
#define HID    4096
#define IMOE   1024
#define ISH    4096
#define NEXP   16
#define NPAIR  8192
#define MAX_MT 80
#define NSTG   3

// ---------------------------------------------------------------------------
// Static device scratch
// ---------------------------------------------------------------------------
static __device__ __half g_xs   [(size_t)T_TOK * HID];
static __device__ __half g_wsgu [(size_t)2*ISH * HID];
static __device__ __half g_wsd  [(size_t)HID * ISH];
static __device__ __half g_wgu  [(size_t)NEXP * 2*IMOE * HID];
static __device__ __half g_wd   [(size_t)NEXP * HID * IMOE];
static __device__ __half g_actsh[(size_t)T_TOK * ISH];
static __device__ __half g_actp [(size_t)NPAIR * IMOE];

static __device__ int   g_counts[NEXP];
static __device__ int   g_offs[NEXP + 1];
static __device__ int   g_cursor[NEXP];
static __device__ int   g_eid[NPAIR];
static __device__ float g_wgt[NPAIR];
static __device__ int   g_perm[NPAIR];
static __device__ float g_wgtp[NPAIR];

static __device__ int   g_te[MAX_MT], g_tp0[MAX_MT], g_tcnt[MAX_MT];
static __device__ int   g_nmt[1];

// ---------------------------------------------------------------------------
// PTX helpers (proven on this harness)
// ---------------------------------------------------------------------------
__device__ __forceinline__ void cp16(uint32_t s, const void* g, int src_bytes) {
    asm volatile("cp.async.cg.shared.global [%0], [%1], 16, %2;\n"
                 :: "r"(s), "l"(g), "r"(src_bytes));
}
__device__ __forceinline__ void cp_commit() { asm volatile("cp.async.commit_group;\n"); }
__device__ __forceinline__ void cp_wait0()  { asm volatile("cp.async.wait_group 0;\n"); }
__device__ __forceinline__ void cp_wait1()  { asm volatile("cp.async.wait_group 1;\n"); }

__device__ __forceinline__ void ldsm4(uint32_t* r, uint32_t a) {
    asm volatile("ldmatrix.sync.aligned.m8n8.x4.shared.b16 {%0,%1,%2,%3}, [%4];\n"
                 : "=r"(r[0]), "=r"(r[1]), "=r"(r[2]), "=r"(r[3]) : "r"(a));
}
__device__ __forceinline__ void ldsm2(uint32_t* r, uint32_t a) {
    asm volatile("ldmatrix.sync.aligned.m8n8.x2.shared.b16 {%0,%1}, [%2];\n"
                 : "=r"(r[0]), "=r"(r[1]) : "r"(a));
}
__device__ __forceinline__ void mma16816(float* c, const uint32_t* a, const uint32_t* b) {
    asm volatile("mma.sync.aligned.m16n8k16.row.col.f32.f16.f16.f32 "
                 "{%0,%1,%2,%3}, {%4,%5,%6,%7}, {%8,%9}, {%0,%1,%2,%3};\n"
                 : "+f"(c[0]), "+f"(c[1]), "+f"(c[2]), "+f"(c[3])
                 : "r"(a[0]), "r"(a[1]), "r"(a[2]), "r"(a[3]), "r"(b[0]), "r"(b[1]));
}

// XOR-swizzled smem offset: 128-byte rows (64 f16), 8x 16B chunks per row.
__device__ __forceinline__ uint32_t swz(uint32_t row, uint32_t chunk) {
    return (row << 7) + (((chunk ^ (row & 7u)) & 7u) << 4);
}

__device__ __forceinline__ float silu_mul(float g, float u) {
    return (g / (1.f + expf(-g))) * u;
}

// ---------------------------------------------------------------------------
// GEMM: CTA tile 128x128x64, 128 threads (2x2 warps, warp tile 64x64),
// 3-stage cp.async (96KB smem, 2 CTAs/SM), fp16 in / fp32 accum.
// MODE 0 dense; MODE 1 grouped, A rows via g_perm; MODE 2 grouped identity.
// EPI 0: fp32 C, 128 cols per tile (B has Nact rows).
// EPI 1: SWIGLU. B has 2*Nact rows (gu), remapped into 32-row slabs
//        [16 g | 16 u] covering act cols nt*64..+63; writes fp16 act.
// EPI 2: fused top-2 combine: atomicAdd(out[g_perm[row]*Nact+col],
//        g_wgtp[row]*acc). (Use with MODE 2.)
// ---------------------------------------------------------------------------
template <int MODE, int EPI>
__global__ void __launch_bounds__(128, 2)
gemm_k(const __half* __restrict__ A, const __half* __restrict__ B,
       void* __restrict__ Cout, int Nact, int K, size_t Bstride, int ntiles)
{
    const int tid  = threadIdx.x;
    const int warp = tid >> 5;
    const int lane = tid & 31;

    int mt_row0, cnt, nt, e = 0;
    if (MODE == 0) {
        int per = 8 * ntiles;                 // m-tile count must be mult of 8
        int chunk = blockIdx.x / per, rem = blockIdx.x - chunk * per;
        mt_row0 = (chunk * 8 + (rem & 7)) << 7;
        nt = rem >> 3;
        cnt = 128;
    } else {
        if ((int)blockIdx.y >= g_nmt[0]) return;
        nt      = blockIdx.x;
        e       = g_te[blockIdx.y];
        mt_row0 = g_tp0[blockIdx.y];
        cnt     = g_tcnt[blockIdx.y];
    }
    const __half* Bp = B + (size_t)e * Bstride;

    extern __shared__ char smem[];   // 3 stages x (A 16KB + B 16KB)
    const uint32_t smB = (uint32_t)__cvta_generic_to_shared(smem);

    const int NIT = K >> 6;

    auto load_tiles = [&](int stage, int it) {
        int kk = it << 6;
        uint32_t aB = smB + stage * 32768;
        uint32_t bB = aB + 16384;
#pragma unroll
        for (int i = 0; i < 8; i++) {
            int lin = i * 128 + tid;
            int row = lin >> 3, ch = lin & 7;
            // A tile row
            size_t ga; int vb = 16;
            if (MODE == 0) {
                ga = (size_t)(mt_row0 + row) * K + kk + ch * 8;
            } else if (MODE == 1) {
                int ok = (row < cnt);
                int rg = ok ? g_perm[mt_row0 + row] : 0;
                vb = ok ? 16 : 0;
                ga = (size_t)rg * K + kk + ch * 8;
            } else {
                int ok = (row < cnt);
                int rg = ok ? (mt_row0 + row) : 0;
                vb = ok ? 16 : 0;
                ga = (size_t)rg * K + kk + ch * 8;
            }
            cp16(aB + swz(row, ch), A + ga, vb);
            // B tile row
            int brow;
            if (EPI == 1) {
                int s = row >> 5, w = row & 31;       // slab s: [16 g | 16 u]
                brow = (w < 16) ? (nt * 64 + s * 16 + w)
                                : (Nact + nt * 64 + s * 16 + (w - 16));
            } else {
                brow = nt * 128 + row;
            }
            cp16(bB + swz(row, ch), Bp + (size_t)brow * K + kk + ch * 8, 16);
        }
        cp_commit();
    };

    float acc[4][8][4];
#pragma unroll
    for (int a = 0; a < 4; a++)
#pragma unroll
        for (int b = 0; b < 8; b++)
#pragma unroll
            for (int c = 0; c < 4; c++) acc[a][b][c] = 0.f;

    const int wm = warp & 1;      // 0..1  (64-row slabs of A)
    const int wn = warp >> 1;     // 0..1  (64-row slabs of B)

    load_tiles(0, 0);
    load_tiles(1, 1);

    for (int it = 0; it < NIT; ++it) {
        if (it == NIT - 1) cp_wait0(); else cp_wait1();
        __syncthreads();          // top barrier: all warps done with it-1 compute
        int cur = it % NSTG;
        if (it + 2 < NIT) load_tiles((it + 2) % NSTG, it + 2);

        uint32_t aB = smB + cur * 32768;
        uint32_t bB = aB + 16384;
#pragma unroll
        for (int kk = 0; kk < 4; kk++) {
            uint32_t afr[4][4], bfr[8][2];
#pragma unroll
            for (int mi = 0; mi < 4; mi++) {
                int row = wm * 64 + mi * 16 + (lane & 15);
                int ch  = kk * 2 + ((lane >> 4) & 1);
                ldsm4(afr[mi], aB + swz(row, ch));
            }
#pragma unroll
            for (int ni = 0; ni < 8; ni++) {
                int row = wn * 64 + ni * 8 + (lane & 7);
                int ch  = kk * 2 + ((lane >> 3) & 1);
                ldsm2(bfr[ni], bB + swz(row, ch));
            }
#pragma unroll
            for (int mi = 0; mi < 4; mi++)
#pragma unroll
                for (int ni = 0; ni < 8; ni++)
                    mma16816(acc[mi][ni], afr[mi], bfr[ni]);
        }
        // no bottom barrier: next iter's top barrier provides the ordering
    }

    // ---------------- epilogue ----------------
#pragma unroll
    for (int mi = 0; mi < 4; mi++) {
        int lr0 = wm * 64 + mi * 16 + (lane >> 2);
        int lr1 = lr0 + 8;
        int v0 = (MODE == 0) || (lr0 < cnt);
        int v1 = (MODE == 0) || (lr1 < cnt);
        if (EPI == 1) {
            __half* act = (__half*)Cout;
            // warp covers slabs 2*wn, 2*wn+1: ni pairs (p, p+2), p in {0,1,4,5}
#pragma unroll
            for (int pi = 0; pi < 4; pi++) {
                const int p = (pi & 1) | ((pi & 2) << 1);   // 0,1,4,5
                size_t col = nt * 64 + (2 * wn + (p >> 2)) * 16
                           + (p & 1) * 8 + 2 * (lane & 3);
                if (v0) {
                    __half2 h = __floats2half2_rn(
                        silu_mul(acc[mi][p][0], acc[mi][p + 2][0]),
                        silu_mul(acc[mi][p][1], acc[mi][p + 2][1]));
                    *(__half2*)&act[(size_t)(mt_row0 + lr0) * Nact + col] = h;
                }
                if (v1) {
                    __half2 h = __floats2half2_rn(
                        silu_mul(acc[mi][p][2], acc[mi][p + 2][2]),
                        silu_mul(acc[mi][p][3], acc[mi][p + 2][3]));
                    *(__half2*)&act[(size_t)(mt_row0 + lr1) * Nact + col] = h;
                }
            }
        } else if (EPI == 2) {
            float* out = (float*)Cout;
            int   t0 = v0 ? g_perm[mt_row0 + lr0] : 0;
            float w0 = v0 ? g_wgtp[mt_row0 + lr0] : 0.f;
            int   t1 = v1 ? g_perm[mt_row0 + lr1] : 0;
            float w1 = v1 ? g_wgtp[mt_row0 + lr1] : 0.f;
#pragma unroll
            for (int ni = 0; ni < 8; ni++) {
                size_t col = nt * 128 + wn * 64 + ni * 8 + 2 * (lane & 3);
                if (v0) {
                    atomicAdd(&out[(size_t)t0 * Nact + col],     w0 * acc[mi][ni][0]);
                    atomicAdd(&out[(size_t)t0 * Nact + col + 1], w0 * acc[mi][ni][1]);
                }
                if (v1) {
                    atomicAdd(&out[(size_t)t1 * Nact + col],     w1 * acc[mi][ni][2]);
                    atomicAdd(&out[(size_t)t1 * Nact + col + 1], w1 * acc[mi][ni][3]);
                }
            }
        } else {
            float* C = (float*)Cout;
#pragma unroll
            for (int ni = 0; ni < 8; ni++) {
                size_t col = nt * 128 + wn * 64 + ni * 8 + 2 * (lane & 3);
                if (v0) {
                    float2 v = make_float2(acc[mi][ni][0], acc[mi][ni][1]);
                    *(float2*)&C[(size_t)(mt_row0 + lr0) * Nact + col] = v;
                }
                if (v1) {
                    float2 v = make_float2(acc[mi][ni][2], acc[mi][ni][3]);
                    *(float2*)&C[(size_t)(mt_row0 + lr1) * Nact + col] = v;
                }
            }
        }
    }
}

// ---------------------------------------------------------------------------
// Elementwise / router kernels
// ---------------------------------------------------------------------------
__global__ void cvt_kernel(const float4* __restrict__ src,
                           uint2* __restrict__ dst, size_t n4)
{
    size_t i = (size_t)blockIdx.x * 256 + threadIdx.x;
    if (i >= n4) return;
    float4 v = src[i];
    __half2 lo = __floats2half2_rn(v.x, v.y);
    __half2 hi = __floats2half2_rn(v.z, v.w);
    uint2 o;
    o.x = *(uint32_t*)&lo;
    o.y = *(uint32_t*)&hi;
    dst[i] = o;
}

__global__ void init_kernel() {
    if (threadIdx.x < NEXP) g_counts[threadIdx.x] = 0;
}

__global__ void router_kernel(const float* __restrict__ x, const float* __restrict__ gw)
{
    __shared__ float slog[NEXP];
    int t = blockIdx.x;
    const float* xr = x + (size_t)t * HID;
    int tid = threadIdx.x;
    int e = tid >> 3, g = tid & 7;
    float s = 0.f;
    const float* w = gw + (size_t)e * HID;
    for (int k = g; k < HID; k += 8) s += xr[k] * w[k];
#pragma unroll
    for (int o = 4; o > 0; o >>= 1) s += __shfl_down_sync(0xffffffffu, s, o, 8);
    if (g == 0) slog[e] = s;
    __syncthreads();
    if (tid == 0) {
        int i0 = 0;
        float b0 = slog[0];
        for (int k = 1; k < NEXP; k++) if (slog[k] > b0) { b0 = slog[k]; i0 = k; }
        int i1 = -1;
        float b1 = -3.4e38f;
        for (int k = 0; k < NEXP; k++) {
            if (k == i0) continue;
            if (slog[k] > b1) { b1 = slog[k]; i1 = k; }
        }
        float m  = fmaxf(b0, b1);
        float e0 = expf(b0 - m), e1 = expf(b1 - m);
        float inv = 1.f / (e0 + e1);
        g_eid[2 * t] = i0;       g_eid[2 * t + 1] = i1;
        g_wgt[2 * t] = e0 * inv; g_wgt[2 * t + 1] = e1 * inv;
        atomicAdd(&g_counts[i0], 1);
        atomicAdd(&g_counts[i1], 1);
    }
}

__global__ void scan_kernel()
{
    if (threadIdx.x != 0 || blockIdx.x != 0) return;
    int off = 0;
    for (int e = 0; e < NEXP; e++) {
        g_offs[e] = off; g_cursor[e] = off; off += g_counts[e];
    }
    g_offs[NEXP] = off;
    int t = 0;
    for (int e = 0; e < NEXP; e++) {
        int c = g_counts[e];
        for (int j = 0; j * 128 < c; j++) {
            g_te[t]  = e;
            g_tp0[t] = g_offs[e] + j * 128;
            int rem  = c - j * 128;
            g_tcnt[t] = rem < 128 ? rem : 128;
            t++;
        }
    }
    g_nmt[0] = t;
}

__global__ void scatter_kernel()
{
    int p = blockIdx.x * 256 + threadIdx.x;
    if (p >= NPAIR) return;
    int e = g_eid[p];
    int pos = atomicAdd(&g_cursor[e], 1);
    g_perm[pos] = p >> 1;
    g_wgtp[pos] = g_wgt[p];
}

// ---------------------------------------------------------------------------
// Launch
// ---------------------------------------------------------------------------
extern "C" void kernel_launch(void* const* d_in, const int* in_sizes, int n_in,
                              void* d_out, int out_size)
{
    const float* x    = (const float*)d_in[0];
    const float* gw   = (const float*)d_in[1];
    const float* wgu  = (const float*)d_in[2];
    const float* wd   = (const float*)d_in[3];
    const float* swgu = (const float*)d_in[4];
    const float* swd  = (const float*)d_in[5];
    float* out = (float*)d_out;

    void *p_xs, *p_wsgu, *p_wsd, *p_wgu, *p_wd, *p_actsh, *p_actp;
    cudaGetSymbolAddress(&p_xs,    g_xs);
    cudaGetSymbolAddress(&p_wsgu,  g_wsgu);
    cudaGetSymbolAddress(&p_wsd,   g_wsd);
    cudaGetSymbolAddress(&p_wgu,   g_wgu);
    cudaGetSymbolAddress(&p_wd,    g_wd);
    cudaGetSymbolAddress(&p_actsh, g_actsh);
    cudaGetSymbolAddress(&p_actp,  g_actp);

    const int SMEM = NSTG * 32768;   // 98304, 2 CTAs/SM
    cudaFuncSetAttribute(gemm_k<0,1>, cudaFuncAttributeMaxDynamicSharedMemorySize, SMEM);
    cudaFuncSetAttribute(gemm_k<0,0>, cudaFuncAttributeMaxDynamicSharedMemorySize, SMEM);
    cudaFuncSetAttribute(gemm_k<1,1>, cudaFuncAttributeMaxDynamicSharedMemorySize, SMEM);
    cudaFuncSetAttribute(gemm_k<2,2>, cudaFuncAttributeMaxDynamicSharedMemorySize, SMEM);

    auto blk4 = [](size_t n) { return (unsigned)((n / 4 + 255) / 256); };

    // fp32 -> fp16 converts
    cvt_kernel<<<blk4((size_t)T_TOK * HID),           256>>>((const float4*)x,    (uint2*)p_xs,   (size_t)T_TOK * HID / 4);
    cvt_kernel<<<blk4((size_t)2 * ISH * HID),         256>>>((const float4*)swgu, (uint2*)p_wsgu, (size_t)2 * ISH * HID / 4);
    cvt_kernel<<<blk4((size_t)HID * ISH),             256>>>((const float4*)swd,  (uint2*)p_wsd,  (size_t)HID * ISH / 4);
    cvt_kernel<<<blk4((size_t)NEXP * 2 * IMOE * HID), 256>>>((const float4*)wgu,  (uint2*)p_wgu,  (size_t)NEXP * 2 * IMOE * HID / 4);
    cvt_kernel<<<blk4((size_t)NEXP * HID * IMOE),     256>>>((const float4*)wd,   (uint2*)p_wd,   (size_t)NEXP * HID * IMOE / 4);

    // router + grouping metadata
    init_kernel<<<1, 32>>>();
    router_kernel<<<T_TOK, 128>>>(x, gw);
    scan_kernel<<<1, 32>>>();
    scatter_kernel<<<(NPAIR + 255) / 256, 256>>>();

    // shared MLP: gate_up (fused swiglu, 64 act cols/tile) then down -> out
    gemm_k<0,1><<<(T_TOK / 128) * (ISH / 64), 128, SMEM>>>(
        (const __half*)p_xs, (const __half*)p_wsgu, p_actsh,
        ISH, HID, 0, ISH / 64);
    gemm_k<0,0><<<(T_TOK / 128) * (HID / 128), 128, SMEM>>>(
        (const __half*)p_actsh, (const __half*)p_wsd, (void*)out,
        HID, ISH, 0, HID / 128);

    // grouped MoE: gate_up (gather + fused swiglu), then down with fused
    // top-2 combine (atomicAdd into out)
    gemm_k<1,1><<<dim3(IMOE / 64, MAX_MT), 128, SMEM>>>(
        (const __half*)p_xs, (const __half*)p_wgu, p_actp,
        IMOE, HID, (size_t)(2 * IMOE) * HID, 0);
    gemm_k<2,2><<<dim3(HID / 128, MAX_MT), 128, SMEM>>>(
        (const __half*)p_actp, (const __half*)p_wd, (void*)out,
        HID, IMOE, (size_t)HID * IMOE, 0);
}

// round 17
// speedup vs baseline: 1.1039x; 1.0027x over previous
#include <cuda_runtime.h>
#include <cuda_bf16.h>
#include <cuda_fp16.h>
#include <cstdint>
#include <math.h>

#define T_TOK  4096
#define HID    4096
#define IMOE   1024
#define ISH    4096
#define NEXP   16
#define NPAIR  8192
#define MAX_MT 80
#define NSTG   3

// ---------------------------------------------------------------------------
// Static device scratch
// ---------------------------------------------------------------------------
static __device__ __half g_xs   [(size_t)T_TOK * HID];
static __device__ __half g_wsgu [(size_t)2*ISH * HID];
static __device__ __half g_wsd  [(size_t)HID * ISH];
static __device__ __half g_wgu  [(size_t)NEXP * 2*IMOE * HID];
static __device__ __half g_wd   [(size_t)NEXP * HID * IMOE];
static __device__ __half g_actsh[(size_t)T_TOK * ISH];
static __device__ __half g_actp [(size_t)NPAIR * IMOE];

static __device__ int   g_counts[NEXP];
static __device__ int   g_offs[NEXP + 1];
static __device__ int   g_cursor[NEXP];
static __device__ int   g_eid[NPAIR];
static __device__ float g_wgt[NPAIR];
static __device__ int   g_perm[NPAIR];
static __device__ float g_wgtp[NPAIR];

static __device__ int   g_te[MAX_MT], g_tp0[MAX_MT], g_tcnt[MAX_MT];
static __device__ int   g_nmt[1];

// ---------------------------------------------------------------------------
// PTX helpers (proven on this harness)
// ---------------------------------------------------------------------------
__device__ __forceinline__ void cp16(uint32_t s, const void* g, int src_bytes) {
    asm volatile("cp.async.cg.shared.global [%0], [%1], 16, %2;\n"
                 :: "r"(s), "l"(g), "r"(src_bytes));
}
__device__ __forceinline__ void cp_commit() { asm volatile("cp.async.commit_group;\n"); }
__device__ __forceinline__ void cp_wait0()  { asm volatile("cp.async.wait_group 0;\n"); }
__device__ __forceinline__ void cp_wait1()  { asm volatile("cp.async.wait_group 1;\n"); }

__device__ __forceinline__ void ldsm4(uint32_t* r, uint32_t a) {
    asm volatile("ldmatrix.sync.aligned.m8n8.x4.shared.b16 {%0,%1,%2,%3}, [%4];\n"
                 : "=r"(r[0]), "=r"(r[1]), "=r"(r[2]), "=r"(r[3]) : "r"(a));
}
__device__ __forceinline__ void ldsm2(uint32_t* r, uint32_t a) {
    asm volatile("ldmatrix.sync.aligned.m8n8.x2.shared.b16 {%0,%1}, [%2];\n"
                 : "=r"(r[0]), "=r"(r[1]) : "r"(a));
}
__device__ __forceinline__ void mma16816(float* c, const uint32_t* a, const uint32_t* b) {
    asm volatile("mma.sync.aligned.m16n8k16.row.col.f32.f16.f16.f32 "
                 "{%0,%1,%2,%3}, {%4,%5,%6,%7}, {%8,%9}, {%0,%1,%2,%3};\n"
                 : "+f"(c[0]), "+f"(c[1]), "+f"(c[2]), "+f"(c[3])
                 : "r"(a[0]), "r"(a[1]), "r"(a[2]), "r"(a[3]), "r"(b[0]), "r"(b[1]));
}

// XOR-swizzled smem offset: 128-byte rows (64 f16), 8x 16B chunks per row.
__device__ __forceinline__ uint32_t swz(uint32_t row, uint32_t chunk) {
    return (row << 7) + (((chunk ^ (row & 7u)) & 7u) << 4);
}

__device__ __forceinline__ float silu_mul(float g, float u) {
    return (g / (1.f + expf(-g))) * u;
}

// ---------------------------------------------------------------------------
// GEMM: CTA tile 128x128x64, 128 threads (2x2 warps, warp tile 64x64),
// 3-stage cp.async (96KB smem, 2 CTAs/SM), fp16 in / fp32 accum.
// MODE 0 dense (x = mtile-chunk raster); MODE 1 grouped, A rows via g_perm;
// MODE 2 grouped identity. Grouped raster: x = m-tile slot, y = ntile, so
// consecutively-scheduled CTAs share the SAME B tile (B is the DRAM-heavy
// operand; A is L2-resident).
// EPI 0: fp32 C, 128 cols per tile (B has Nact rows).
// EPI 1: SWIGLU. B has 2*Nact rows (gu), remapped into 32-row slabs
//        [16 g | 16 u] covering act cols nt*64..+63; writes fp16 act.
// EPI 2: fused top-2 combine: atomicAdd(out[g_perm[row]*Nact+col],
//        g_wgtp[row]*acc). (Use with MODE 2.)
// ---------------------------------------------------------------------------
template <int MODE, int EPI>
__global__ void __launch_bounds__(128, 2)
gemm_k(const __half* __restrict__ A, const __half* __restrict__ B,
       void* __restrict__ Cout, int Nact, int K, size_t Bstride, int ntiles)
{
    const int tid  = threadIdx.x;
    const int warp = tid >> 5;
    const int lane = tid & 31;

    int mt_row0, cnt, nt, e = 0;
    if (MODE == 0) {
        int per = 8 * ntiles;                 // m-tile count must be mult of 8
        int chunk = blockIdx.x / per, rem = blockIdx.x - chunk * per;
        mt_row0 = (chunk * 8 + (rem & 7)) << 7;
        nt = rem >> 3;
        cnt = 128;
    } else {
        if ((int)blockIdx.x >= g_nmt[0]) return;   // x = m-tile slot
        nt      = blockIdx.y;                      // y = ntile (B reuse across x)
        e       = g_te[blockIdx.x];
        mt_row0 = g_tp0[blockIdx.x];
        cnt     = g_tcnt[blockIdx.x];
    }
    const __half* Bp = B + (size_t)e * Bstride;

    extern __shared__ char smem[];   // 3 stages x (A 16KB + B 16KB)
    const uint32_t smB = (uint32_t)__cvta_generic_to_shared(smem);

    const int NIT = K >> 6;

    auto load_tiles = [&](int stage, int it) {
        int kk = it << 6;
        uint32_t aB = smB + stage * 32768;
        uint32_t bB = aB + 16384;
#pragma unroll
        for (int i = 0; i < 8; i++) {
            int lin = i * 128 + tid;
            int row = lin >> 3, ch = lin & 7;
            // A tile row
            size_t ga; int vb = 16;
            if (MODE == 0) {
                ga = (size_t)(mt_row0 + row) * K + kk + ch * 8;
            } else if (MODE == 1) {
                int ok = (row < cnt);
                int rg = ok ? g_perm[mt_row0 + row] : 0;
                vb = ok ? 16 : 0;
                ga = (size_t)rg * K + kk + ch * 8;
            } else {
                int ok = (row < cnt);
                int rg = ok ? (mt_row0 + row) : 0;
                vb = ok ? 16 : 0;
                ga = (size_t)rg * K + kk + ch * 8;
            }
            cp16(aB + swz(row, ch), A + ga, vb);
            // B tile row
            int brow;
            if (EPI == 1) {
                int s = row >> 5, w = row & 31;       // slab s: [16 g | 16 u]
                brow = (w < 16) ? (nt * 64 + s * 16 + w)
                                : (Nact + nt * 64 + s * 16 + (w - 16));
            } else {
                brow = nt * 128 + row;
            }
            cp16(bB + swz(row, ch), Bp + (size_t)brow * K + kk + ch * 8, 16);
        }
        cp_commit();
    };

    float acc[4][8][4];
#pragma unroll
    for (int a = 0; a < 4; a++)
#pragma unroll
        for (int b = 0; b < 8; b++)
#pragma unroll
            for (int c = 0; c < 4; c++) acc[a][b][c] = 0.f;

    const int wm = warp & 1;      // 0..1  (64-row slabs of A)
    const int wn = warp >> 1;     // 0..1  (64-row slabs of B)

    load_tiles(0, 0);
    load_tiles(1, 1);

    for (int it = 0; it < NIT; ++it) {
        if (it == NIT - 1) cp_wait0(); else cp_wait1();
        __syncthreads();          // top barrier: all warps done with it-1 compute
        int cur = it % NSTG;
        if (it + 2 < NIT) load_tiles((it + 2) % NSTG, it + 2);

        uint32_t aB = smB + cur * 32768;
        uint32_t bB = aB + 16384;
#pragma unroll
        for (int kk = 0; kk < 4; kk++) {
            uint32_t afr[4][4], bfr[8][2];
#pragma unroll
            for (int mi = 0; mi < 4; mi++) {
                int row = wm * 64 + mi * 16 + (lane & 15);
                int ch  = kk * 2 + ((lane >> 4) & 1);
                ldsm4(afr[mi], aB + swz(row, ch));
            }
#pragma unroll
            for (int ni = 0; ni < 8; ni++) {
                int row = wn * 64 + ni * 8 + (lane & 7);
                int ch  = kk * 2 + ((lane >> 3) & 1);
                ldsm2(bfr[ni], bB + swz(row, ch));
            }
#pragma unroll
            for (int mi = 0; mi < 4; mi++)
#pragma unroll
                for (int ni = 0; ni < 8; ni++)
                    mma16816(acc[mi][ni], afr[mi], bfr[ni]);
        }
        // no bottom barrier: next iter's top barrier provides the ordering
    }

    // ---------------- epilogue ----------------
#pragma unroll
    for (int mi = 0; mi < 4; mi++) {
        int lr0 = wm * 64 + mi * 16 + (lane >> 2);
        int lr1 = lr0 + 8;
        int v0 = (MODE == 0) || (lr0 < cnt);
        int v1 = (MODE == 0) || (lr1 < cnt);
        if (EPI == 1) {
            __half* act = (__half*)Cout;
            // warp covers slabs 2*wn, 2*wn+1: ni pairs (p, p+2), p in {0,1,4,5}
#pragma unroll
            for (int pi = 0; pi < 4; pi++) {
                const int p = (pi & 1) | ((pi & 2) << 1);   // 0,1,4,5
                size_t col = nt * 64 + (2 * wn + (p >> 2)) * 16
                           + (p & 1) * 8 + 2 * (lane & 3);
                if (v0) {
                    __half2 h = __floats2half2_rn(
                        silu_mul(acc[mi][p][0], acc[mi][p + 2][0]),
                        silu_mul(acc[mi][p][1], acc[mi][p + 2][1]));
                    *(__half2*)&act[(size_t)(mt_row0 + lr0) * Nact + col] = h;
                }
                if (v1) {
                    __half2 h = __floats2half2_rn(
                        silu_mul(acc[mi][p][2], acc[mi][p + 2][2]),
                        silu_mul(acc[mi][p][3], acc[mi][p + 2][3]));
                    *(__half2*)&act[(size_t)(mt_row0 + lr1) * Nact + col] = h;
                }
            }
        } else if (EPI == 2) {
            float* out = (float*)Cout;
            int   t0 = v0 ? g_perm[mt_row0 + lr0] : 0;
            float w0 = v0 ? g_wgtp[mt_row0 + lr0] : 0.f;
            int   t1 = v1 ? g_perm[mt_row0 + lr1] : 0;
            float w1 = v1 ? g_wgtp[mt_row0 + lr1] : 0.f;
#pragma unroll
            for (int ni = 0; ni < 8; ni++) {
                size_t col = nt * 128 + wn * 64 + ni * 8 + 2 * (lane & 3);
                if (v0) {
                    atomicAdd(&out[(size_t)t0 * Nact + col],     w0 * acc[mi][ni][0]);
                    atomicAdd(&out[(size_t)t0 * Nact + col + 1], w0 * acc[mi][ni][1]);
                }
                if (v1) {
                    atomicAdd(&out[(size_t)t1 * Nact + col],     w1 * acc[mi][ni][2]);
                    atomicAdd(&out[(size_t)t1 * Nact + col + 1], w1 * acc[mi][ni][3]);
                }
            }
        } else {
            float* C = (float*)Cout;
#pragma unroll
            for (int ni = 0; ni < 8; ni++) {
                size_t col = nt * 128 + wn * 64 + ni * 8 + 2 * (lane & 3);
                if (v0) {
                    float2 v = make_float2(acc[mi][ni][0], acc[mi][ni][1]);
                    *(float2*)&C[(size_t)(mt_row0 + lr0) * Nact + col] = v;
                }
                if (v1) {
                    float2 v = make_float2(acc[mi][ni][2], acc[mi][ni][3]);
                    *(float2*)&C[(size_t)(mt_row0 + lr1) * Nact + col] = v;
                }
            }
        }
    }
}

// ---------------------------------------------------------------------------
// Elementwise / router kernels
// ---------------------------------------------------------------------------
__global__ void cvt_kernel(const float4* __restrict__ src,
                           uint2* __restrict__ dst, size_t n4)
{
    size_t i = (size_t)blockIdx.x * 256 + threadIdx.x;
    if (i >= n4) return;
    float4 v = src[i];
    __half2 lo = __floats2half2_rn(v.x, v.y);
    __half2 hi = __floats2half2_rn(v.z, v.w);
    uint2 o;
    o.x = *(uint32_t*)&lo;
    o.y = *(uint32_t*)&hi;
    dst[i] = o;
}

__global__ void init_kernel() {
    if (threadIdx.x < NEXP) g_counts[threadIdx.x] = 0;
}

__global__ void router_kernel(const float* __restrict__ x, const float* __restrict__ gw)
{
    __shared__ float slog[NEXP];
    int t = blockIdx.x;
    const float* xr = x + (size_t)t * HID;
    int tid = threadIdx.x;
    int e = tid >> 3, g = tid & 7;
    float s = 0.f;
    const float* w = gw + (size_t)e * HID;
    for (int k = g; k < HID; k += 8) s += xr[k] * w[k];
#pragma unroll
    for (int o = 4; o > 0; o >>= 1) s += __shfl_down_sync(0xffffffffu, s, o, 8);
    if (g == 0) slog[e] = s;
    __syncthreads();
    if (tid == 0) {
        int i0 = 0;
        float b0 = slog[0];
        for (int k = 1; k < NEXP; k++) if (slog[k] > b0) { b0 = slog[k]; i0 = k; }
        int i1 = -1;
        float b1 = -3.4e38f;
        for (int k = 0; k < NEXP; k++) {
            if (k == i0) continue;
            if (slog[k] > b1) { b1 = slog[k]; i1 = k; }
        }
        float m  = fmaxf(b0, b1);
        float e0 = expf(b0 - m), e1 = expf(b1 - m);
        float inv = 1.f / (e0 + e1);
        g_eid[2 * t] = i0;       g_eid[2 * t + 1] = i1;
        g_wgt[2 * t] = e0 * inv; g_wgt[2 * t + 1] = e1 * inv;
        atomicAdd(&g_counts[i0], 1);
        atomicAdd(&g_counts[i1], 1);
    }
}

__global__ void scan_kernel()
{
    if (threadIdx.x != 0 || blockIdx.x != 0) return;
    int off = 0;
    for (int e = 0; e < NEXP; e++) {
        g_offs[e] = off; g_cursor[e] = off; off += g_counts[e];
    }
    g_offs[NEXP] = off;
    int t = 0;
    for (int e = 0; e < NEXP; e++) {
        int c = g_counts[e];
        for (int j = 0; j * 128 < c; j++) {
            g_te[t]  = e;
            g_tp0[t] = g_offs[e] + j * 128;
            int rem  = c - j * 128;
            g_tcnt[t] = rem < 128 ? rem : 128;
            t++;
        }
    }
    g_nmt[0] = t;
}

__global__ void scatter_kernel()
{
    int p = blockIdx.x * 256 + threadIdx.x;
    if (p >= NPAIR) return;
    int e = g_eid[p];
    int pos = atomicAdd(&g_cursor[e], 1);
    g_perm[pos] = p >> 1;
    g_wgtp[pos] = g_wgt[p];
}

// ---------------------------------------------------------------------------
// Launch
// ---------------------------------------------------------------------------
extern "C" void kernel_launch(void* const* d_in, const int* in_sizes, int n_in,
                              void* d_out, int out_size)
{
    const float* x    = (const float*)d_in[0];
    const float* gw   = (const float*)d_in[1];
    const float* wgu  = (const float*)d_in[2];
    const float* wd   = (const float*)d_in[3];
    const float* swgu = (const float*)d_in[4];
    const float* swd  = (const float*)d_in[5];
    float* out = (float*)d_out;

    void *p_xs, *p_wsgu, *p_wsd, *p_wgu, *p_wd, *p_actsh, *p_actp;
    cudaGetSymbolAddress(&p_xs,    g_xs);
    cudaGetSymbolAddress(&p_wsgu,  g_wsgu);
    cudaGetSymbolAddress(&p_wsd,   g_wsd);
    cudaGetSymbolAddress(&p_wgu,   g_wgu);
    cudaGetSymbolAddress(&p_wd,    g_wd);
    cudaGetSymbolAddress(&p_actsh, g_actsh);
    cudaGetSymbolAddress(&p_actp,  g_actp);

    const int SMEM = NSTG * 32768;   // 98304, 2 CTAs/SM
    cudaFuncSetAttribute(gemm_k<0,1>, cudaFuncAttributeMaxDynamicSharedMemorySize, SMEM);
    cudaFuncSetAttribute(gemm_k<0,0>, cudaFuncAttributeMaxDynamicSharedMemorySize, SMEM);
    cudaFuncSetAttribute(gemm_k<1,1>, cudaFuncAttributeMaxDynamicSharedMemorySize, SMEM);
    cudaFuncSetAttribute(gemm_k<2,2>, cudaFuncAttributeMaxDynamicSharedMemorySize, SMEM);

    auto blk4 = [](size_t n) { return (unsigned)((n / 4 + 255) / 256); };

    // fp32 -> fp16 converts
    cvt_kernel<<<blk4((size_t)T_TOK * HID),           256>>>((const float4*)x,    (uint2*)p_xs,   (size_t)T_TOK * HID / 4);
    cvt_kernel<<<blk4((size_t)2 * ISH * HID),         256>>>((const float4*)swgu, (uint2*)p_wsgu, (size_t)2 * ISH * HID / 4);
    cvt_kernel<<<blk4((size_t)HID * ISH),             256>>>((const float4*)swd,  (uint2*)p_wsd,  (size_t)HID * ISH / 4);
    cvt_kernel<<<blk4((size_t)NEXP * 2 * IMOE * HID), 256>>>((const float4*)wgu,  (uint2*)p_wgu,  (size_t)NEXP * 2 * IMOE * HID / 4);
    cvt_kernel<<<blk4((size_t)NEXP * HID * IMOE),     256>>>((const float4*)wd,   (uint2*)p_wd,   (size_t)NEXP * HID * IMOE / 4);

    // router + grouping metadata
    init_kernel<<<1, 32>>>();
    router_kernel<<<T_TOK, 128>>>(x, gw);
    scan_kernel<<<1, 32>>>();
    scatter_kernel<<<(NPAIR + 255) / 256, 256>>>();

    // shared MLP: gate_up (fused swiglu, 64 act cols/tile) then down -> out
    gemm_k<0,1><<<(T_TOK / 128) * (ISH / 64), 128, SMEM>>>(
        (const __half*)p_xs, (const __half*)p_wsgu, p_actsh,
        ISH, HID, 0, ISH / 64);
    gemm_k<0,0><<<(T_TOK / 128) * (HID / 128), 128, SMEM>>>(
        (const __half*)p_actsh, (const __half*)p_wsd, (void*)out,
        HID, ISH, 0, HID / 128);

    // grouped MoE: gate_up (gather + fused swiglu), then down with fused
    // top-2 combine (atomicAdd into out). Raster: x = m-tile slot, y = ntile
    // so consecutive CTAs share the B tile (expert weights = DRAM-heavy).
    gemm_k<1,1><<<dim3(MAX_MT, IMOE / 64), 128, SMEM>>>(
        (const __half*)p_xs, (const __half*)p_wgu, p_actp,
        IMOE, HID, (size_t)(2 * IMOE) * HID, 0);
    gemm_k<2,2><<<dim3(MAX_MT, HID / 128), 128, SMEM>>>(
        (const __half*)p_actp, (const __half*)p_wd, (void*)out,
        HID, IMOE, (size_t)HID * IMOE, 0);
}